// round 8
// baseline (speedup 1.0000x reference)
#include <cuda_runtime.h>
#include <cstdint>

// Problem shape (fixed by the dataset)
#define B_BATCH 4
#define E_EDGES 320000
#define N_NODES 10000
#define F_FEAT  64
#define NBINS   (B_BATCH * N_NODES)   // 40000
#define CAP     64                    // bucket capacity per (b,node); lambda=32
#define OVF_MAX 32768

// Scratch (allocation-free: __device__ globals)
__device__ int d_cnt[NBINS];               // per-(b,node) edge count
__device__ int d_bucket[NBINS * CAP];      // edge ids per bin (10.24 MB)
__device__ int d_ovf_cnt;                  // overflow count
__device__ int d_ovf[OVF_MAX];             // overflow edge ids (b*E+e)

// ---------------------------------------------------------------- K0: reset
__global__ __launch_bounds__(256) void reset_kernel() {
    int i = blockIdx.x * blockDim.x + threadIdx.x;
    if (i < NBINS) d_cnt[i] = 0;
    if (i == 0)    d_ovf_cnt = 0;
}

// ---------------------------------------------------------------- K1: fill
// One thread per edge: bin it by destination node.
__global__ __launch_bounds__(256) void fill_kernel(const int* __restrict__ start_idx) {
    const int b = blockIdx.y;
    const int e = blockIdx.x * blockDim.x + threadIdx.x;
    if (e >= E_EDGES) return;

    const int be   = b * E_EDGES + e;
    const int node = __ldg(start_idx + be);
    const int bn   = b * N_NODES + node;

    const int slot = atomicAdd(&d_cnt[bn], 1);
    if (slot < CAP) {
        d_bucket[bn * CAP + slot] = e;
    } else {
        int p = atomicAdd(&d_ovf_cnt, 1);
        if (p < OVF_MAX) d_ovf[p] = be;
    }
}

// ---------------------------------------------------------------- K2: gather
// 16-lane group per (b,node). Lane = one float4 of the 64-feature vector.
// Edge ids for a bin are contiguous -> broadcast int4 reads; per edge the
// group issues one fully-coalesced 256B msg read. Pure float4 stores to out
// (covers every element, so no separate zero-init pass).
__global__ __launch_bounds__(256) void gather_kernel(
    const float4* __restrict__ msg,   // [B, E, 16] float4
    float4*       __restrict__ out)   // [B, N, 16] float4
{
    const int t     = blockIdx.x * blockDim.x + threadIdx.x;
    const int group = t >> 4;          // (b,node) bin id
    const int f4    = t & 15;
    if (group >= NBINS) return;

    const int b    = group / N_NODES;
    const long long msg_base = (long long)b * E_EDGES;
    const int cnt  = min(d_cnt[group], CAP);

    const int4* bvec = reinterpret_cast<const int4*>(d_bucket + group * CAP);

    float4 acc = make_float4(0.f, 0.f, 0.f, 0.f);

    const int cnt4 = cnt >> 2;            // full groups of 4 edges
    int4 ids = (cnt4 > 0) ? bvec[0] : make_int4(0, 0, 0, 0);
    for (int s4 = 0; s4 < cnt4; ++s4) {
        const int4 cur = ids;
        if (s4 + 1 < cnt4) ids = bvec[s4 + 1];   // prefetch next ids

        const float4 m0 = __ldg(msg + (msg_base + cur.x) * 16 + f4);
        const float4 m1 = __ldg(msg + (msg_base + cur.y) * 16 + f4);
        const float4 m2 = __ldg(msg + (msg_base + cur.z) * 16 + f4);
        const float4 m3 = __ldg(msg + (msg_base + cur.w) * 16 + f4);

        acc.x += m0.x + m1.x + m2.x + m3.x;
        acc.y += m0.y + m1.y + m2.y + m3.y;
        acc.z += m0.z + m1.z + m2.z + m3.z;
        acc.w += m0.w + m1.w + m2.w + m3.w;
    }
    for (int s = cnt4 * 4; s < cnt; ++s) {
        const int e = d_bucket[group * CAP + s];
        const float4 m = __ldg(msg + (msg_base + e) * 16 + f4);
        acc.x += m.x; acc.y += m.y; acc.z += m.z; acc.w += m.w;
    }

    out[(long long)group * 16 + f4] = acc;
}

// ---------------------------------------------------------------- K3: overflow
// Runs AFTER gather's plain stores; RED-adds any edges that overflowed their
// bucket (statistically ~never at CAP=64, but guarantees correctness).
__global__ __launch_bounds__(256) void overflow_kernel(
    const float4* __restrict__ msg,
    const int*    __restrict__ start_idx,
    float*        __restrict__ out)
{
    const int total = min(d_ovf_cnt, OVF_MAX);
    for (int i = blockIdx.x * blockDim.x + threadIdx.x; i < total;
         i += gridDim.x * blockDim.x) {
        const int be   = d_ovf[i];
        const int b    = be / E_EDGES;
        const int node = __ldg(start_idx + be);
        const float4* m = msg + (long long)be * 16;
        float* dst = out + ((long long)b * N_NODES + node) * F_FEAT;
#pragma unroll
        for (int f4 = 0; f4 < 16; ++f4) {
            const float4 v = m[f4];
            asm volatile(
                "red.global.add.v4.f32 [%0], {%1, %2, %3, %4};"
                :: "l"(dst + f4 * 4), "f"(v.x), "f"(v.y), "f"(v.z), "f"(v.w)
                : "memory");
        }
    }
}

extern "C" void kernel_launch(void* const* d_in, const int* in_sizes, int n_in,
                              void* d_out, int out_size) {
    const float4* msg = (const float4*)d_in[0];   // msg_vectors [B,E,F] f32
    const int*    idx = (const int*)d_in[1];      // start_indices [B,E] i32
    // d_in[2] = h_v, unused by the reference computation
    float* out = (float*)d_out;                   // [B,N,F] f32

    // K0: reset counters
    reset_kernel<<<(NBINS + 255) / 256, 256>>>();

    // K1: bin edges by destination node
    dim3 fgrid((E_EDGES + 255) / 256, B_BATCH);   // (1250, 4)
    fill_kernel<<<fgrid, 256>>>(idx);

    // K2: gather-sum per (b,node); writes every output element
    const int gthreads = NBINS * 16;              // 640,000
    gather_kernel<<<(gthreads + 255) / 256, 256>>>(msg, (float4*)out);

    // K3: fold in (rare) overflow edges via RED
    overflow_kernel<<<16, 256>>>(msg, idx, out);
}

// round 9
// speedup vs baseline: 1.2110x; 1.2110x over previous
#include <cuda_runtime.h>
#include <cstdint>

// Problem shape (fixed by the dataset)
#define B_BATCH 4
#define E_EDGES 320000
#define N_NODES 10000
#define F_FEAT  64

// 16 threads cover the 64-feature vector of an edge (one float4 each).
// Each thread processes 8 CONSECUTIVE edges: 2 vectorized int4 index loads
// plus 8 LDG.128 msg loads are all issued up front (MLP ~ 10) before the 8
// no-return vectorized reductions. msg is read-once -> streaming (__ldcs)
// so the L2-resident output lines stay hot for the RED RMWs.
__global__ __launch_bounds__(256) void scatter_add_kernel(
    const float4* __restrict__ msg,       // [B, E, 16] float4
    const int*    __restrict__ start_idx, // [B, E]
    float*        __restrict__ out)       // [B, N, 64]
{
    const int b  = blockIdx.y;
    const int t  = blockIdx.x * blockDim.x + threadIdx.x;
    const int f4 = t & 15;          // which float4 of the feature vector
    const int e0 = (t >> 4) * 8;    // first of 8 edges handled by this thread
    if (e0 >= E_EDGES) return;

    const long long base = (long long)b * E_EDGES;

    // Vectorized index loads (lanes 0-15 broadcast the same int4).
    const int4 ia = __ldg(reinterpret_cast<const int4*>(start_idx + base + e0));
    const int4 ib = __ldg(reinterpret_cast<const int4*>(start_idx + base + e0 + 4));
    const int node[8] = { ia.x, ia.y, ia.z, ia.w, ib.x, ib.y, ib.z, ib.w };

    // Front-batched streaming msg loads. Within a warp each load covers two
    // contiguous 256B segments (lanes 0-15 edge g, lanes 16-31 edge g+8).
    float4 v[8];
#pragma unroll
    for (int u = 0; u < 8; ++u) {
        v[u] = __ldcs(msg + (base + e0 + u) * 16 + f4);
    }

#pragma unroll
    for (int u = 0; u < 8; ++u) {
        float* dst = out + ((long long)b * N_NODES + node[u]) * F_FEAT + f4 * 4;
        asm volatile(
            "red.global.add.v4.f32 [%0], {%1, %2, %3, %4};"
            :: "l"(dst), "f"(v[u].x), "f"(v[u].y), "f"(v[u].z), "f"(v[u].w)
            : "memory");
    }
}

extern "C" void kernel_launch(void* const* d_in, const int* in_sizes, int n_in,
                              void* d_out, int out_size) {
    const float4* msg = (const float4*)d_in[0];   // msg_vectors [B,E,F] f32
    const int*    idx = (const int*)d_in[1];      // start_indices [B,E] i32
    // d_in[2] = h_v, unused by the reference computation
    float* out = (float*)d_out;                   // [B,N,F] f32

    // 1) zero the output (harness poisons it with 0xAA). Memset node is
    //    graph-capturable and faster than a zeroing kernel.
    cudaMemsetAsync(out, 0, (size_t)out_size * sizeof(float), 0);

    // 2) scatter-add: E*16/8 threads per batch, batch on grid.y
    const int threads_per_batch = E_EDGES * 16 / 8;   // 640,000
    dim3 grid(threads_per_batch / 256, B_BATCH);      // (2500, 4)
    scatter_add_kernel<<<grid, 256>>>(msg, idx, out);
}